// round 14
// baseline (speedup 1.0000x reference)
#include <cuda_runtime.h>
#include <cuda_bf16.h>

// NeighborSearch_batch via 33x33 uniform grid — R6 configuration (measured
// best) with row_splits fused into the query kernel via acq_rel atomics
// (NO threadfence -> no CCTL.IVALL L1 flush, unlike R13).
// B=8, n=9225 data pts, m=4096 queries, d=2, radius=0.03
// Output (float32): neighbors_index [B, m, 64] then row_splits [B, m+1].

#define BATCH  8
#define NPTS   9225
#define NQ     4096
#define MAXN   64
#define GRID   33
#define NCELLS (GRID * GRID)
#define CAP    64     // per-query accept capacity (reference: observed max ~50)

#define LPQ    4      // lanes per query
#define QPB    32     // queries per CTA
#define QTPB   (LPQ * QPB)       // 128 threads
#define CTAS_PER_B (NQ / QPB)    // 128 query CTAs per batch
#define ARRIVALS_PER_B (CTAS_PER_B * QPB)  // 4096 arrivals per batch per run

// data binning (global, read by query kernel)
__device__ int    g_cnt_cell[BATCH * NCELLS];
__device__ int    g_start   [BATCH * NCELLS];
__device__ float4 g_pts     [BATCH * NPTS];   // (x, y, dn, idx-as-float-bits)
// binned queries: (x, y, qn, orig-idx-as-float-bits)
__device__ float4 g_qpts    [BATCH * NQ];
// per-query neighbor counts (original query order)
__device__ int    g_counts  [BATCH * NQ];
// per-batch done counters (monotone; never reset -> graph-replay safe)
__device__ unsigned int g_done[BATCH];

__device__ __forceinline__ int cell_of(float x, float y) {
    int cx = (int)(x * (float)GRID); if (cx > GRID - 1) cx = GRID - 1; if (cx < 0) cx = 0;
    int cy = (int)(y * (float)GRID); if (cy > GRID - 1) cy = GRID - 1; if (cy < 0) cy = 0;
    return cy * GRID + cx;
}

__device__ __forceinline__ int ldcg_i32(const int* p) {
    int v;
    asm volatile("ld.global.cg.s32 %0, [%1];" : "=r"(v) : "l"(p));
    return v;
}

// acq_rel add: orders this thread's prior global stores before the add
// (release), and subsequent reads after it (acquire). No L1 flush.
__device__ __forceinline__ unsigned atom_acqrel_add(unsigned* p, unsigned v) {
    unsigned old;
    asm volatile("atom.acq_rel.gpu.global.add.u32 %0, [%1], %2;"
                 : "=r"(old) : "l"(p), "r"(v) : "memory");
    return old;
}

// One CTA per (batch, kind): blocks 0..7 bin data, 8..15 bin queries.
// Count (smem atomics) -> block scan (1089) -> scatter (smem cursors).
__global__ void __launch_bounds__(1024)
bin_kernel(const float* __restrict__ data,
           const float* __restrict__ queries)
{
    __shared__ int scnt[NCELLS];
    __shared__ int scur[NCELLS];
    __shared__ int warp_sums[32];

    const int isq = blockIdx.x >= BATCH;
    const int b   = blockIdx.x - (isq ? BATCH : 0);
    const int n   = isq ? NQ : NPTS;
    const float* src = isq ? (queries + (size_t)b * NQ * 2)
                           : (data    + (size_t)b * NPTS * 2);
    float4* dst = isq ? (g_qpts + (size_t)b * NQ)
                      : (g_pts  + (size_t)b * NPTS);

    const int t = threadIdx.x;
    const int lane = t & 31, wid = t >> 5;

    for (int i = t; i < NCELLS; i += 1024) scnt[i] = 0;
    __syncthreads();

    // pass 1: count
    for (int i = t; i < n; i += 1024) {
        const float2 p = ((const float2*)src)[i];
        atomicAdd(&scnt[cell_of(p.x, p.y)], 1);
    }
    __syncthreads();

    // exclusive block scan over NCELLS=1089 (2 elems/thread)
    const int i0 = 2 * t, i1 = 2 * t + 1;
    const int c0 = (i0 < NCELLS) ? scnt[i0] : 0;
    const int c1 = (i1 < NCELLS) ? scnt[i1] : 0;
    const int total = c0 + c1;

    int x = total;
    #pragma unroll
    for (int o = 1; o < 32; o <<= 1) {
        int y = __shfl_up_sync(0xFFFFFFFFu, x, o);
        if (lane >= o) x += y;
    }
    if (lane == 31) warp_sums[wid] = x;
    __syncthreads();
    if (wid == 0) {
        int w = warp_sums[lane];
        #pragma unroll
        for (int o = 1; o < 32; o <<= 1) {
            int y = __shfl_up_sync(0xFFFFFFFFu, w, o);
            if (lane >= o) w += y;
        }
        warp_sums[lane] = w;
    }
    __syncthreads();

    const int excl = (x - total) + (wid > 0 ? warp_sums[wid - 1] : 0);
    if (i0 < NCELLS) {
        scur[i0] = excl;
        if (!isq) { g_start[b * NCELLS + i0] = excl; g_cnt_cell[b * NCELLS + i0] = c0; }
    }
    if (i1 < NCELLS) {
        scur[i1] = excl + c0;
        if (!isq) { g_start[b * NCELLS + i1] = excl + c0; g_cnt_cell[b * NCELLS + i1] = c1; }
    }
    __syncthreads();

    // pass 2: scatter (norm term computed with reference rounding:
    // nn = RN(RN(x*x) + RN(y*y)) matches jnp.sum(v*v, axis=-1))
    for (int i = t; i < n; i += 1024) {
        const float2 p = ((const float2*)src)[i];
        const float nn = __fadd_rn(__fmul_rn(p.x, p.x), __fmul_rn(p.y, p.y));
        const int c = cell_of(p.x, p.y);
        const int pos = atomicAdd(&scur[c], 1);
        dst[pos] = make_float4(p.x, p.y, nn, __int_as_float(i));
    }
}

// 4 lanes cooperate on one query (R6 structure, verbatim accept loop).
// Fused row_splits: sub==0 threads arrive on a per-batch acq_rel counter
// after storing their count; the 4096th arriver's CTA scans the batch.
__global__ void __launch_bounds__(QTPB)
query_kernel(const float* __restrict__ radius,
             float* __restrict__ nbr_idx,
             float* __restrict__ row_splits)
{
    __shared__ int cand[CAP][QPB + 1];   // stride 33: conflict-free
    __shared__ int s_scan[4];
    __shared__ int s_flag;

    const int tid   = threadIdx.x;
    const int sub   = tid & (LPQ - 1);       // 0..3 within group
    const int qslot = tid >> 2;               // 0..31 query slot in CTA
    const int shift = (tid & 31) & ~(LPQ - 1);
    const unsigned gmask = 0xFu << shift;

    if (tid == 0) s_flag = 0;
    __syncthreads();

    const int b = blockIdx.y;
    const int qbin = blockIdx.x * QPB + qslot;

    const float4 qv = g_qpts[(size_t)b * NQ + qbin];  // 4-lane broadcast
    const float q0 = qv.x;
    const float q1 = qv.y;
    const float qn = qv.z;
    const int   oq = __float_as_int(qv.w);

    const float r  = radius[0];
    const float r2 = __fmul_rn(r, r);
    int reach = (int)ceilf(r * (float)GRID);
    if (reach < 1) reach = 1;

    int cx = (int)(q0 * (float)GRID); if (cx > GRID - 1) cx = GRID - 1; if (cx < 0) cx = 0;
    int cy = (int)(q1 * (float)GRID); if (cy > GRID - 1) cy = GRID - 1; if (cy < 0) cy = 0;
    const int x0 = max(0, cx - reach), x1 = min(GRID - 1, cx + reach);
    const int y0 = max(0, cy - reach), y1 = min(GRID - 1, cy + reach);

    const float4* pts = g_pts + (size_t)b * NPTS;
    const int* starts = g_start    + b * NCELLS;
    const int* cnts   = g_cnt_cell + b * NCELLS;

    int cnt = 0;

    for (int gy = y0; gy <= y1; ++gy) {
        const int ca = gy * GRID + x0;
        const int cb = gy * GRID + x1;
        const int s = starts[ca];
        const int e = starts[cb] + cnts[cb];
        // group-uniform trip count; lanes take i = ib+sub (coalesced 64B)
        for (int ib = s; ib < e; ib += LPQ) {
            const int i = ib + sub;
            bool acc = false;
            int idx = 0;
            if (i < e) {
                const float4 p = pts[i];
                // cross = RN(RN(q0*px) + RN(q1*py)); 2*cross exact (self-add)
                const float cr = __fadd_rn(__fmul_rn(q0, p.x), __fmul_rn(q1, p.y));
                // v = RN(RN(qn + dn) - 2*cross)
                const float v  = __fsub_rn(__fadd_rn(qn, p.z), __fadd_rn(cr, cr));
                acc = (v <= r2);
                idx = __float_as_int(p.w);
            }
            const unsigned bal = __ballot_sync(gmask, acc);
            const unsigned nib = (bal >> shift) & 0xFu;
            if (acc) {
                const int s2 = cnt + __popc(nib & ((1u << sub) - 1u));
                if (s2 < CAP) cand[s2][qslot] = idx;
            }
            cnt += __popc(nib);
        }
    }

    float* out = nbr_idx + ((size_t)(b * NQ + oq)) * MAXN;
    const int k = cnt < CAP ? cnt : CAP;

    // -1 fill (slots k..63), split across the 4 lanes
    for (int s = k + sub; s < MAXN; s += LPQ) out[s] = -1.0f;

    // rank-selection emit: rank_i = #{j : v_j < v_i} is a permutation of
    // 0..k-1 (indices distinct) -> sorted output, scatter-order independent.
    for (int i = sub; i < k; i += LPQ) {
        const int v = cand[i][qslot];
        int rank = 0;
        #pragma unroll 4
        for (int j = 0; j < k; ++j)
            rank += (cand[j][qslot] < v) ? 1 : 0;
        out[rank] = (float)v;   // rank <= k-1 < MAXN <= CAP
    }

    // count store + release-arrive (same thread: store ordered before add)
    if (sub == 0) {
        g_counts[b * NQ + oq] = cnt;
        const unsigned old = atom_acqrel_add(&g_done[b], 1u);
        if ((old % ARRIVALS_PER_B) == (ARRIVALS_PER_B - 1)) s_flag = 1;
    }
    __syncthreads();
    if (!s_flag) return;

    // last CTA for batch b: compute row_splits (counts via L2, post-acquire)
    {
        const int lane = tid & 31, wid = tid >> 5;
        const int* cc = g_counts + b * NQ;
        const int base = tid * 32;

        int vals[32];
        int tot = 0;
        #pragma unroll 8
        for (int i = 0; i < 32; ++i) {
            vals[i] = ldcg_i32(cc + base + i);
            tot += vals[i];
        }

        int x2 = tot;
        #pragma unroll
        for (int o = 1; o < 32; o <<= 1) {
            const int y = __shfl_up_sync(0xFFFFFFFFu, x2, o);
            if (lane >= o) x2 += y;
        }
        if (lane == 31) s_scan[wid] = x2;
        __syncthreads();
        if (wid == 0 && lane < 4) {
            int w = s_scan[lane];
            #pragma unroll
            for (int o = 1; o < 4; o <<= 1) {
                const int y = __shfl_up_sync(0x0000000Fu, w, o);
                if (lane >= o) w += y;
            }
            s_scan[lane] = w;
        }
        __syncthreads();

        int run = (x2 - tot) + (wid > 0 ? s_scan[wid - 1] : 0);
        float* rs = row_splits + b * (NQ + 1);
        if (tid == 0) rs[0] = 0.0f;
        #pragma unroll 8
        for (int i = 0; i < 32; ++i) {
            run += vals[i];
            rs[base + 1 + i] = (float)run;
        }
    }
}

extern "C" void kernel_launch(void* const* d_in, const int* in_sizes, int n_in,
                              void* d_out, int out_size)
{
    const float* data    = (const float*)d_in[0];   // [8, 9225, 2]
    const float* queries = (const float*)d_in[1];   // [8, 4096, 2]
    const float* radius  = (const float*)d_in[2];   // scalar

    float* nbr_idx    = (float*)d_out;                          // [8, 4096, 64]
    float* row_splits = nbr_idx + (size_t)BATCH * NQ * MAXN;    // [8, 4097]

    bin_kernel<<<2 * BATCH, 1024>>>(data, queries);

    dim3 qgrid(NQ / QPB, BATCH);
    query_kernel<<<qgrid, QTPB>>>(radius, nbr_idx, row_splits);
}